// round 16
// baseline (speedup 1.0000x reference)
#include <cuda_runtime.h>
#include <cuda_bf16.h>
#include <cstdint>

// ---------------- problem constants ----------------
#define MAX_N 20000
#define NPAD  20096          // 157 * 128 (covers 313*64 = 20032)
#define MAX_E 320000
#define R_REL 5
#define IN_DIM 64
#define IN0 112              // 64 + 32 + 16
#define HID 256
#define NEG_SLOPE 0.2f

// ---------------- static device scratch (zero-initialized at module load) ------
__device__ float g_h0[(size_t)MAX_N * IN0];
__device__ float g_agg[(size_t)MAX_N * IN_DIM];
__device__ float g_xl[(size_t)R_REL * MAX_N * HID];
__device__ float g_xr[(size_t)R_REL * MAX_N * HID];
__device__ float g_out1[(size_t)MAX_N * HID];
__device__ float g_out2[(size_t)MAX_N * HID];
__device__ float g_bsum[2][HID];
// bf16-split GEMM operands
__device__ __nv_bfloat16 g_Ah[(size_t)NPAD * 256];
__device__ __nv_bfloat16 g_Al[(size_t)NPAD * 256];
__device__ __nv_bfloat16 g_Wth[(size_t)2 * 10 * 256 * 256];  // [l][z][n][k]
__device__ __nv_bfloat16 g_Wtl[(size_t)2 * 10 * 256 * 256];
// CSR scratch; g_cnt zero at load + tail-restored every call
__device__ int g_cnt[R_REL * MAX_N];
__device__ int g_cur[R_REL * MAX_N];
__device__ int g_off[R_REL * MAX_N];
__device__ int g_csr[(size_t)R_REL * MAX_E];

__device__ __forceinline__ uint32_t smem_u32(const void* p) {
    uint32_t a;
    asm("{ .reg .u64 t; cvta.to.shared.u64 t, %1; cvt.u32.u64 %0, t; }" : "=r"(a) : "l"(p));
    return a;
}

// RULE (hard-learned, R6/R10/R11/R12): NEVER pass a __device__ global symbol as
// a host-side kernel argument — ATS silently dereferences the host shadow and
// the driver grows a 128MiB pool -> harness rule violation. Select device
// buffers via integer flags inside device code only.
#define LDSM_X4(r0, r1, r2, r3, addr) \
    asm volatile("ldmatrix.sync.aligned.m8n8.x4.shared.b16 {%0,%1,%2,%3}, [%4];" \
        : "=r"(r0), "=r"(r1), "=r"(r2), "=r"(r3) : "r"(addr))

#define MMA16816(c, A, B) asm volatile( \
    "mma.sync.aligned.m16n8k16.row.col.f32.bf16.bf16.f32 " \
    "{%0,%1,%2,%3}, {%4,%5,%6,%7}, {%8,%9}, {%0,%1,%2,%3};" \
    : "+f"((c)[0]), "+f"((c)[1]), "+f"((c)[2]), "+f"((c)[3]) \
    : "r"((A)[0]), "r"((A)[1]), "r"((A)[2]), "r"((A)[3]), "r"((B)[0]), "r"((B)[1]))

#define EX2A(d, s)  asm("ex2.approx.f32 %0, %1;" : "=f"(d) : "f"(s))
#define RCPA(d, s)  asm("rcp.approx.f32 %0, %1;" : "=f"(d) : "f"(s))

// ---------------- CSR build ----------------
__global__ void k_hist(const int* __restrict__ ei, int N, int E) {
    int i = blockIdx.x * blockDim.x + threadIdx.x;
    if (i >= R_REL * E) return;
    int r = i / E, e = i - r * E;
    int dst = ei[(size_t)(r * 2 + 1) * E + e];
    atomicAdd(&g_cnt[r * N + dst], 1);
}

__global__ void __launch_bounds__(1024) k_scan(int N) {
    int r = blockIdx.x;
    __shared__ int sh[1024];
    int t = threadIdx.x;
    int carry = 0;
    int nchunk = (N + 1023) / 1024;
    for (int c = 0; c < nchunk; c++) {
        int i = c * 1024 + t;
        int v = (i < N) ? g_cnt[r * N + i] : 0;
        sh[t] = v;
        __syncthreads();
        #pragma unroll
        for (int off = 1; off < 1024; off <<= 1) {
            int x = (t >= off) ? sh[t - off] : 0;
            __syncthreads();
            if (t >= off) sh[t] += x;
            __syncthreads();
        }
        int incl = sh[t];
        if (i < N) {
            int excl = incl - v + carry;
            g_off[r * N + i] = excl;
            g_cur[r * N + i] = excl;
        }
        carry += sh[1023];
        __syncthreads();
    }
}

__global__ void k_scatter(const int* __restrict__ ei, int N, int E) {
    int i = blockIdx.x * blockDim.x + threadIdx.x;
    if (i >= R_REL * E) return;
    int r = i / E, e = i - r * E;
    int src = ei[(size_t)(r * 2 + 0) * E + e];
    int dst = ei[(size_t)(r * 2 + 1) * E + e];
    int pos = atomicAdd(&g_cur[r * N + dst], 1);
    g_csr[(size_t)r * E + pos] = src;
}

__global__ void k_zero_cnt(int N) {
    int i = blockIdx.x * blockDim.x + threadIdx.x;
    if (i < R_REL * N) g_cnt[i] = 0;
}

// ---------------- PEARL mean aggregation ----------------
__global__ void __launch_bounds__(256) k_pearl(const float* __restrict__ x, int N, int E) {
    int w = (blockIdx.x * blockDim.x + threadIdx.x) >> 5;
    int lane = threadIdx.x & 31;
    if (w >= N) return;
    int d = w;
    float ax = 0.f, ay = 0.f;
    int deg = 0;
    #pragma unroll
    for (int r = 0; r < R_REL; r++) {
        int beg = g_off[r * N + d], num = g_cnt[r * N + d];
        deg += num;
        const int* srcs = g_csr + (size_t)r * E + beg;
        for (int base = 0; base < num; base += 32) {
            int my = (base + lane < num) ? srcs[base + lane] : 0;
            int lim = min(32, num - base);
            for (int q = 0; q < lim; q++) {
                int src = __shfl_sync(0xffffffffu, my, q);
                float2 v = *(const float2*)(x + (size_t)src * IN_DIM + lane * 2);
                ax += v.x; ay += v.y;
            }
        }
    }
    float inv = 1.f / fmaxf((float)deg, 1.f);
    *(float2*)(g_agg + (size_t)d * IN_DIM + lane * 2) = make_float2(ax * inv, ay * inv);
}

__global__ void k_bsum(const float* __restrict__ b0, const float* __restrict__ b1) {
    int c = threadIdx.x;
    float s0 = 0.f, s1 = 0.f;
    #pragma unroll
    for (int r = 0; r < R_REL; r++) { s0 += b0[r * HID + c]; s1 += b1[r * HID + c]; }
    g_bsum[0][c] = s0; g_bsum[1][c] = s1;
}

// build h0, 8 nodes/block
__global__ void __launch_bounds__(256) k_build_h0(const float* __restrict__ x,
                                                  const int* __restrict__ date,
                                                  const float* __restrict__ Wp,
                                                  const float* __restrict__ bp, int N) {
    __shared__ float sWp[IN_DIM * 32];
    __shared__ float sam[8][IN_DIM];
    int t = threadIdx.x;
    int n0 = blockIdx.x * 8;
    for (int i = t; i < IN_DIM * 32; i += 256) sWp[i] = Wp[i];
    for (int i = t; i < 8 * IN_DIM; i += 256) {
        int u = i >> 6, k = i & 63;
        int n = n0 + u;
        sam[u][k] = (n < N) ? g_agg[(size_t)n * IN_DIM + k] : 0.f;
    }
    __syncthreads();
    int u2 = t >> 7, t1 = t & 127;
    #pragma unroll
    for (int ui = 0; ui < 4; ui++) {
        int u = ui * 2 + u2;
        int n = n0 + u;
        if (n < N) {
            float* hrow = g_h0 + (size_t)n * IN0;
            if (t1 < 64) {
                hrow[t1] = x[(size_t)n * IN_DIM + t1];
            } else if (t1 < 96) {
                int c = t1 - 64;
                float acc = bp[c];
                #pragma unroll
                for (int k = 0; k < IN_DIM; k++) acc += sam[u][k] * sWp[k * 32 + c];
                hrow[64 + c] = tanhf(acc);
            } else if (t1 < 112) {
                int j = t1 - 96;
                int jj = j & 7;
                float tt = (float)date[n] / 10000.f;
                float div = expf(-(float)(2 * jj) * (logf(10000.f) / 16.f));
                float a = tt * div;
                hrow[96 + j] = (j < 8) ? sinf(a) : cosf(a);
            }
        }
    }
}

// ---------------- bf16 split conversions ----------------
// which=0 -> src g_h0 (K=112), which=1 -> src g_out1 (K=256). Device-side select.
__global__ void __launch_bounds__(256) k_cvtA(int which, int srcK, int N) {
    const float* src = which ? g_out1 : g_h0;
    int row = blockIdx.x;
    int k = threadIdx.x;
    float v = (row < N && k < srcK) ? src[(size_t)row * srcK + k] : 0.f;
    __nv_bfloat16 h = __float2bfloat16(v);
    __nv_bfloat16 l = __float2bfloat16(v - __bfloat162float(h));
    g_Ah[(size_t)row * 256 + k] = h;
    g_Al[(size_t)row * 256 + k] = l;
}

__global__ void __launch_bounds__(256) k_cvtW(const float* __restrict__ Wl0,
                                              const float* __restrict__ Wr0,
                                              const float* __restrict__ Wl1,
                                              const float* __restrict__ Wr1) {
    int n = blockIdx.x;
    int z = blockIdx.y;
    int l = blockIdx.z;
    int k = threadIdx.x;
    int srcK = (l == 0) ? IN0 : HID;
    const float* W = (l == 0) ? ((z < 5) ? Wl0 : Wr0) : ((z < 5) ? Wl1 : Wr1);
    int zz = z % 5;
    float v = (k < srcK) ? W[((size_t)zz * srcK + k) * HID + n] : 0.f;
    __nv_bfloat16 h = __float2bfloat16(v);
    __nv_bfloat16 lo = __float2bfloat16(v - __bfloat162float(h));
    size_t di = ((size_t)(l * 10 + z) * 256 + n) * 256 + k;
    g_Wth[di] = h;
    g_Wtl[di] = lo;
}

// ---------------- bf16-split GEMM via mma.sync (R13 config: 64x64, measured) ---
// CTA: 128 threads (4 warps), tile 64(M) x 64(N); warp tile 32x32.
// D = Ah*Bh + Ah*Bl + Al*Bh, fp32 accum (dropped Al*Bl <= 2^-16 rel).
__global__ void __launch_bounds__(128) k_mma(int Nn, int layer, int K) {
    __shared__ __nv_bfloat16 sAh[64 * 40];
    __shared__ __nv_bfloat16 sAl[64 * 40];
    __shared__ __nv_bfloat16 sBh[64 * 40];
    __shared__ __nv_bfloat16 sBl[64 * 40];
    int tid = threadIdx.x;
    int lane = tid & 31, wid = tid >> 5;
    int wm = wid & 1, wn = wid >> 1;               // warp tile: (wm*32, wn*32)
    int row0 = blockIdx.x * 64;
    int nb = blockIdx.y * 64;
    int z = blockIdx.z;

    uint32_t uAh = smem_u32(sAh), uAl = smem_u32(sAl);
    uint32_t uBh = smem_u32(sBh), uBl = smem_u32(sBl);

    const uint4* Ah4 = (const uint4*)g_Ah;
    const uint4* Al4 = (const uint4*)g_Al;
    const uint4* Wh4 = (const uint4*)g_Wth;
    const uint4* Wl4 = (const uint4*)g_Wtl;
    size_t wrow0 = (size_t)(layer * 10 + z) * 256 + nb;

    int lr = lane & 7, g = lane >> 3;
    uint32_t offA = (uint32_t)((wm * 32 + (g & 1) * 8 + lr) * 80 + ((g >> 1) * 8) * 2);
    uint32_t offB = (uint32_t)((wn * 32 + (g >> 1) * 8 + lr) * 80 + ((g & 1) * 8) * 2);

    float acc[2][4][4] = {};
    for (int k0 = 0; k0 < K; k0 += 32) {
        #pragma unroll
        for (int it = 0; it < 2; it++) {
            int idx = tid + it * 128;              // 0..255
            int row = idx >> 2, q = idx & 3;
            size_t ga = (size_t)(row0 + row) * 32 + (k0 >> 3) + q;
            size_t gb = (wrow0 + row) * 32 + (k0 >> 3) + q;
            *(uint4*)((char*)sAh + row * 80 + q * 16) = Ah4[ga];
            *(uint4*)((char*)sAl + row * 80 + q * 16) = Al4[ga];
            *(uint4*)((char*)sBh + row * 80 + q * 16) = Wh4[gb];
            *(uint4*)((char*)sBl + row * 80 + q * 16) = Wl4[gb];
        }
        __syncthreads();
        #pragma unroll
        for (int ks = 0; ks < 32; ks += 16) {
            uint32_t kb = (uint32_t)(ks * 2);
            uint32_t a[2][4], bh[4][2], bl[4][2];
            #pragma unroll
            for (int j8 = 0; j8 < 2; j8++) {
                LDSM_X4(bh[2 * j8][0], bh[2 * j8][1], bh[2 * j8 + 1][0], bh[2 * j8 + 1][1],
                        uBh + offB + kb + (uint32_t)(j8 * 16 * 80));
                LDSM_X4(bl[2 * j8][0], bl[2 * j8][1], bl[2 * j8 + 1][0], bl[2 * j8 + 1][1],
                        uBl + offB + kb + (uint32_t)(j8 * 16 * 80));
            }
            #pragma unroll
            for (int i = 0; i < 2; i++)
                LDSM_X4(a[i][0], a[i][1], a[i][2], a[i][3],
                        uAh + offA + kb + (uint32_t)(i * 16 * 80));
            #pragma unroll
            for (int i = 0; i < 2; i++)
                #pragma unroll
                for (int j = 0; j < 4; j++) { MMA16816(acc[i][j], a[i], bh[j]); }
            #pragma unroll
            for (int i = 0; i < 2; i++)
                #pragma unroll
                for (int j = 0; j < 4; j++) { MMA16816(acc[i][j], a[i], bl[j]); }
            #pragma unroll
            for (int i = 0; i < 2; i++)
                LDSM_X4(a[i][0], a[i][1], a[i][2], a[i][3],
                        uAl + offA + kb + (uint32_t)(i * 16 * 80));
            #pragma unroll
            for (int i = 0; i < 2; i++)
                #pragma unroll
                for (int j = 0; j < 4; j++) { MMA16816(acc[i][j], a[i], bh[j]); }
        }
        __syncthreads();
    }
    float* base = ((z < 5) ? g_xl : g_xr) + (size_t)(z % 5) * Nn * HID;
    #pragma unroll
    for (int i = 0; i < 2; i++) {
        #pragma unroll
        for (int j = 0; j < 4; j++) {
            int m = row0 + wm * 32 + i * 16 + (lane >> 2);
            int nn = nb + wn * 32 + j * 8 + (lane & 3) * 2;
            if (m < Nn)
                *(float2*)&base[(size_t)m * HID + nn] = make_float2(acc[i][j][0], acc[i][j][1]);
            if (m + 8 < Nn)
                *(float2*)&base[(size_t)(m + 8) * HID + nn] = make_float2(acc[i][j][2], acc[i][j][3]);
        }
    }
}

// ---------------- fused GATv2 layer — scalar lrelu-fold + ex2 ------------------
// lrelu(m) = 0.6m + 0.4|m| (exact for slope 0.2); log2(e) folded into the
// attention coefficients so exp() is a single ex2.approx. NO f32x2 packing
// (R15 showed the pack/unpack overhead regresses). Otherwise identical to the
// measured-best R13 k_gat.
__global__ void __launch_bounds__(256) k_gat(const float* __restrict__ att,
                                             int N, int E, int layer, int which) {
    const unsigned F = 0xffffffffu;
    int w = (blockIdx.x * blockDim.x + threadIdx.x) >> 5;
    int lane = threadIdx.x & 31;
    if (w >= N) return;
    int d = w;
    float4 A0 = *(const float4*)&g_bsum[layer][lane * 8];
    float4 A1 = *(const float4*)&g_bsum[layer][lane * 8 + 4];
    const float LOG2E = 1.44269504088896340736f;
    for (int r = 0; r < R_REL; r++) {
        int beg = g_off[r * N + d], num = g_cnt[r * N + d];
        const float* xlbase = g_xl + (size_t)r * N * HID;
        const float4* xr4 = (const float4*)(g_xr + ((size_t)r * N + d) * HID + lane * 8);
        float4 r0 = xr4[0], r1 = xr4[1];
        const float4* at4 = (const float4*)(att + r * HID + lane * 8);
        float4 af0 = at4[0], af1 = at4[1];
        float c6 = 0.6f * LOG2E, c4 = 0.4f * LOG2E;
        float4 s60 = make_float4(af0.x * c6, af0.y * c6, af0.z * c6, af0.w * c6);
        float4 s61 = make_float4(af1.x * c6, af1.y * c6, af1.z * c6, af1.w * c6);
        float4 s40 = make_float4(af0.x * c4, af0.y * c4, af0.z * c4, af0.w * c4);
        float4 s41 = make_float4(af1.x * c4, af1.y * c4, af1.z * c4, af1.w * c4);
        float t0 = 0.f, t1 = 0.f, t2 = 0.f, t3 = 0.f;
        float t4 = 0.f, t5 = 0.f, t6 = 0.f, t7 = 0.f;
        float denom = 0.f;
        const int* srcs = g_csr + (size_t)r * E + beg;
        for (int base = 0; base < num; base += 32) {
            int my = (base + lane < num) ? srcs[base + lane] : 0;
            int lim = min(32, num - base);
            for (int q = 0; q < lim; q++) {
                int src = __shfl_sync(F, my, q);
                const float4* xl = (const float4*)(xlbase + (size_t)src * HID + lane * 8);
                float4 l0 = xl[0], l1 = xl[1];
                float m0 = l0.x + r0.x, m1 = l0.y + r0.y, m2 = l0.z + r0.z, m3 = l0.w + r0.w;
                float m4 = l1.x + r1.x, m5 = l1.y + r1.y, m6 = l1.z + r1.z, m7 = l1.w + r1.w;
                float s = s60.x * m0 + s40.x * fabsf(m0);
                s = fmaf(s60.y, m1, fmaf(s40.y, fabsf(m1), s));
                s = fmaf(s60.z, m2, fmaf(s40.z, fabsf(m2), s));
                s = fmaf(s60.w, m3, fmaf(s40.w, fabsf(m3), s));
                s = fmaf(s61.x, m4, fmaf(s41.x, fabsf(m4), s));
                s = fmaf(s61.y, m5, fmaf(s41.y, fabsf(m5), s));
                s = fmaf(s61.z, m6, fmaf(s41.z, fabsf(m6), s));
                s = fmaf(s61.w, m7, fmaf(s41.w, fabsf(m7), s));
                s += __shfl_xor_sync(F, s, 4);
                s += __shfl_xor_sync(F, s, 2);
                s += __shfl_xor_sync(F, s, 1);
                float ex;
                EX2A(ex, s);                       // score already in log2 domain
                denom += ex;
                t0 = fmaf(ex, l0.x, t0); t1 = fmaf(ex, l0.y, t1);
                t2 = fmaf(ex, l0.z, t2); t3 = fmaf(ex, l0.w, t3);
                t4 = fmaf(ex, l1.x, t4); t5 = fmaf(ex, l1.y, t5);
                t6 = fmaf(ex, l1.z, t6); t7 = fmaf(ex, l1.w, t7);
            }
        }
        float inv;
        RCPA(inv, denom + 1e-16f);                 // num==0: t==0 -> contributes 0
        A0.x += t0 * inv; A0.y += t1 * inv; A0.z += t2 * inv; A0.w += t3 * inv;
        A1.x += t4 * inv; A1.y += t5 * inv; A1.z += t6 * inv; A1.w += t7 * inv;
    }
    A0.x = fmaxf(A0.x, 0.f); A0.y = fmaxf(A0.y, 0.f);
    A0.z = fmaxf(A0.z, 0.f); A0.w = fmaxf(A0.w, 0.f);
    A1.x = fmaxf(A1.x, 0.f); A1.y = fmaxf(A1.y, 0.f);
    A1.z = fmaxf(A1.z, 0.f); A1.w = fmaxf(A1.w, 0.f);
    float* outbuf = which ? g_out2 : g_out1;
    float* hp = outbuf + (size_t)d * HID + lane * 8;
    *(float4*)hp = A0; *(float4*)(hp + 4) = A1;
}

// output MLP
__global__ void __launch_bounds__(256) k_mlp(const float* __restrict__ W1,
                                             const float* __restrict__ b1,
                                             const float* __restrict__ W2,
                                             const float* __restrict__ b2,
                                             float* __restrict__ out, int N) {
    __shared__ float sh[HID][17];
    __shared__ float so[16][129];
    int t = threadIdx.x;
    int n0 = blockIdx.x * 16;
    for (int i = t; i < 16 * HID; i += 256) {
        int u = i >> 8, c = i & (HID - 1);
        int n = n0 + u;
        sh[c][u] = (n < N) ? g_out2[(size_t)n * HID + c] : 0.f;
    }
    __syncthreads();
    int ct = t & 127, ug = t >> 7;
    float acc[8];
    float bb = b1[ct];
    #pragma unroll
    for (int j = 0; j < 8; j++) acc[j] = bb;
    for (int k = 0; k < HID; k++) {
        float wv = W1[k * 128 + ct];
        #pragma unroll
        for (int j = 0; j < 8; j++) acc[j] += sh[k][ug * 8 + j] * wv;
    }
    #pragma unroll
    for (int j = 0; j < 8; j++) so[ug * 8 + j][ct] = fmaxf(acc[j], 0.f);
    __syncthreads();
    if (t < 48) {
        int u = t / 3, j = t - u * 3;
        int n = n0 + u;
        if (n < N) {
            float a = b2[j];
            #pragma unroll 4
            for (int k = 0; k < 128; k++) a += so[u][k] * W2[k * 3 + j];
            out[(size_t)n * 3 + j] = a;
        }
    }
}

// ---------------- launch ----------------
extern "C" void kernel_launch(void* const* d_in, const int* in_sizes, int n_in,
                              void* d_out, int out_size) {
    const float* x     = (const float*)d_in[0];
    const int*   date  = (const int*)d_in[1];
    const int*   ei    = (const int*)d_in[2];
    const float* pW    = (const float*)d_in[3];
    const float* pb    = (const float*)d_in[4];
    const float* Wl0   = (const float*)d_in[5];
    const float* Wr0   = (const float*)d_in[6];
    const float* att0  = (const float*)d_in[7];
    const float* b0    = (const float*)d_in[8];
    const float* Wl1   = (const float*)d_in[9];
    const float* Wr1   = (const float*)d_in[10];
    const float* att1  = (const float*)d_in[11];
    const float* b1    = (const float*)d_in[12];
    const float* oW1   = (const float*)d_in[16];
    const float* ob1   = (const float*)d_in[17];
    const float* oW2   = (const float*)d_in[18];
    const float* ob2   = (const float*)d_in[19];
    float* out = (float*)d_out;

    int N = in_sizes[0] / IN_DIM;
    int E = in_sizes[2] / (R_REL * 2);

    // ---- CSR build ----
    k_hist<<<(R_REL * E + 255) / 256, 256>>>(ei, N, E);
    k_scan<<<R_REL, 1024>>>(N);
    k_scatter<<<(R_REL * E + 255) / 256, 256>>>(ei, N, E);

    // ---- PE + h0 ----
    k_pearl<<<(N * 32 + 255) / 256, 256>>>(x, N, E);           // profiled slot
    k_bsum<<<1, HID>>>(b0, b1);
    k_build_h0<<<(N + 7) / 8, 256>>>(x, date, pW, pb, N);

    // ---- weight conversion ----
    dim3 wgrid(256, 10, 2);
    k_cvtW<<<wgrid, 256>>>(Wl0, Wr0, Wl1, Wr1);

    int mtiles = (N + 63) / 64;
    dim3 mma_grid(mtiles, 4, 10);
    int gat_grid = (N * 32 + 255) / 256;

    // ---- GNN layer 0 (K padded 112 -> 128) ----
    k_cvtA<<<NPAD, 256>>>(0, IN0, N);
    k_mma<<<mma_grid, 128>>>(N, 0, 128);
    k_gat<<<gat_grid, 256>>>(att0, N, E, 0, 0);

    // ---- GNN layer 1 (K = 256) ----
    k_cvtA<<<NPAD, 256>>>(1, HID, N);
    k_mma<<<mma_grid, 128>>>(N, 1, 256);
    k_gat<<<gat_grid, 256>>>(att1, N, E, 1, 1);

    // ---- output MLP ----
    k_mlp<<<(N + 15) / 16, 256>>>(oW1, ob1, oW2, ob2, out, N);

    // ---- tail: restore g_cnt ----
    k_zero_cnt<<<(R_REL * N + 255) / 256, 256>>>(N);
}

// round 17
// speedup vs baseline: 1.1431x; 1.1431x over previous
#include <cuda_runtime.h>
#include <cuda_fp16.h>
#include <cstdint>

// ---------------- problem constants ----------------
#define MAX_N 20000
#define NPAD  20096          // 157 * 128 (covers 313*64 = 20032)
#define MAX_E 320000
#define R_REL 5
#define IN_DIM 64
#define IN0 112              // 64 + 32 + 16
#define HID 256
#define NEG_SLOPE 0.2f

// ---------------- static device scratch (zero-initialized at module load) ------
__device__ float g_h0[(size_t)MAX_N * IN0];
__device__ float g_agg[(size_t)MAX_N * IN_DIM];
__device__ float g_xl[(size_t)R_REL * MAX_N * HID];
__device__ float g_xr[(size_t)R_REL * MAX_N * HID];
__device__ float g_out1[(size_t)MAX_N * HID];
__device__ float g_out2[(size_t)MAX_N * HID];
__device__ float g_bsum[2][HID];
// fp16-split GEMM operands
__device__ __half g_Ah[(size_t)NPAD * 256];
__device__ __half g_Al[(size_t)NPAD * 256];
__device__ __half g_Wth[(size_t)2 * 10 * 256 * 256];  // [l][z][n][k]
__device__ __half g_Wtl[(size_t)2 * 10 * 256 * 256];
// CSR scratch; g_cnt zero at load + tail-restored every call
__device__ int g_cnt[R_REL * MAX_N];
__device__ int g_cur[R_REL * MAX_N];
__device__ int g_off[R_REL * MAX_N];
__device__ int g_csr[(size_t)R_REL * MAX_E];

__device__ __forceinline__ float lrelu(float m) { return m > 0.f ? m : NEG_SLOPE * m; }

__device__ __forceinline__ uint32_t smem_u32(const void* p) {
    uint32_t a;
    asm("{ .reg .u64 t; cvta.to.shared.u64 t, %1; cvt.u32.u64 %0, t; }" : "=r"(a) : "l"(p));
    return a;
}

// RULE (hard-learned, R6/R10/R11/R12): NEVER pass a __device__ global symbol as
// a host-side kernel argument — ATS silently dereferences the host shadow and
// the driver grows a 128MiB pool -> harness rule violation. Select device
// buffers via integer flags inside device code only.
#define LDSM_X4(r0, r1, r2, r3, addr) \
    asm volatile("ldmatrix.sync.aligned.m8n8.x4.shared.b16 {%0,%1,%2,%3}, [%4];" \
        : "=r"(r0), "=r"(r1), "=r"(r2), "=r"(r3) : "r"(addr))

#define MMA16816(c, A, B) asm volatile( \
    "mma.sync.aligned.m16n8k16.row.col.f32.f16.f16.f32 " \
    "{%0,%1,%2,%3}, {%4,%5,%6,%7}, {%8,%9}, {%0,%1,%2,%3};" \
    : "+f"((c)[0]), "+f"((c)[1]), "+f"((c)[2]), "+f"((c)[3]) \
    : "r"((A)[0]), "r"((A)[1]), "r"((A)[2]), "r"((A)[3]), "r"((B)[0]), "r"((B)[1]))

// ---------------- CSR build ----------------
__global__ void k_hist(const int* __restrict__ ei, int N, int E) {
    int i = blockIdx.x * blockDim.x + threadIdx.x;
    if (i >= R_REL * E) return;
    int r = i / E, e = i - r * E;
    int dst = ei[(size_t)(r * 2 + 1) * E + e];
    atomicAdd(&g_cnt[r * N + dst], 1);
}

__global__ void __launch_bounds__(1024) k_scan(int N) {
    int r = blockIdx.x;
    __shared__ int sh[1024];
    int t = threadIdx.x;
    int carry = 0;
    int nchunk = (N + 1023) / 1024;
    for (int c = 0; c < nchunk; c++) {
        int i = c * 1024 + t;
        int v = (i < N) ? g_cnt[r * N + i] : 0;
        sh[t] = v;
        __syncthreads();
        #pragma unroll
        for (int off = 1; off < 1024; off <<= 1) {
            int x = (t >= off) ? sh[t - off] : 0;
            __syncthreads();
            if (t >= off) sh[t] += x;
            __syncthreads();
        }
        int incl = sh[t];
        if (i < N) {
            int excl = incl - v + carry;
            g_off[r * N + i] = excl;
            g_cur[r * N + i] = excl;
        }
        carry += sh[1023];
        __syncthreads();
    }
}

__global__ void k_scatter(const int* __restrict__ ei, int N, int E) {
    int i = blockIdx.x * blockDim.x + threadIdx.x;
    if (i >= R_REL * E) return;
    int r = i / E, e = i - r * E;
    int src = ei[(size_t)(r * 2 + 0) * E + e];
    int dst = ei[(size_t)(r * 2 + 1) * E + e];
    int pos = atomicAdd(&g_cur[r * N + dst], 1);
    g_csr[(size_t)r * E + pos] = src;
}

__global__ void k_zero_cnt(int N) {
    int i = blockIdx.x * blockDim.x + threadIdx.x;
    if (i < R_REL * N) g_cnt[i] = 0;
}

// ---------------- PEARL mean aggregation ----------------
__global__ void __launch_bounds__(256) k_pearl(const float* __restrict__ x, int N, int E) {
    int w = (blockIdx.x * blockDim.x + threadIdx.x) >> 5;
    int lane = threadIdx.x & 31;
    if (w >= N) return;
    int d = w;
    float ax = 0.f, ay = 0.f;
    int deg = 0;
    #pragma unroll
    for (int r = 0; r < R_REL; r++) {
        int beg = g_off[r * N + d], num = g_cnt[r * N + d];
        deg += num;
        const int* srcs = g_csr + (size_t)r * E + beg;
        for (int base = 0; base < num; base += 32) {
            int my = (base + lane < num) ? srcs[base + lane] : 0;
            int lim = min(32, num - base);
            for (int q = 0; q < lim; q++) {
                int src = __shfl_sync(0xffffffffu, my, q);
                float2 v = *(const float2*)(x + (size_t)src * IN_DIM + lane * 2);
                ax += v.x; ay += v.y;
            }
        }
    }
    float inv = 1.f / fmaxf((float)deg, 1.f);
    *(float2*)(g_agg + (size_t)d * IN_DIM + lane * 2) = make_float2(ax * inv, ay * inv);
}

__global__ void k_bsum(const float* __restrict__ b0, const float* __restrict__ b1) {
    int c = threadIdx.x;
    float s0 = 0.f, s1 = 0.f;
    #pragma unroll
    for (int r = 0; r < R_REL; r++) { s0 += b0[r * HID + c]; s1 += b1[r * HID + c]; }
    g_bsum[0][c] = s0; g_bsum[1][c] = s1;
}

// build h0, 8 nodes/block
__global__ void __launch_bounds__(256) k_build_h0(const float* __restrict__ x,
                                                  const int* __restrict__ date,
                                                  const float* __restrict__ Wp,
                                                  const float* __restrict__ bp, int N) {
    __shared__ float sWp[IN_DIM * 32];
    __shared__ float sam[8][IN_DIM];
    int t = threadIdx.x;
    int n0 = blockIdx.x * 8;
    for (int i = t; i < IN_DIM * 32; i += 256) sWp[i] = Wp[i];
    for (int i = t; i < 8 * IN_DIM; i += 256) {
        int u = i >> 6, k = i & 63;
        int n = n0 + u;
        sam[u][k] = (n < N) ? g_agg[(size_t)n * IN_DIM + k] : 0.f;
    }
    __syncthreads();
    int u2 = t >> 7, t1 = t & 127;
    #pragma unroll
    for (int ui = 0; ui < 4; ui++) {
        int u = ui * 2 + u2;
        int n = n0 + u;
        if (n < N) {
            float* hrow = g_h0 + (size_t)n * IN0;
            if (t1 < 64) {
                hrow[t1] = x[(size_t)n * IN_DIM + t1];
            } else if (t1 < 96) {
                int c = t1 - 64;
                float acc = bp[c];
                #pragma unroll
                for (int k = 0; k < IN_DIM; k++) acc += sam[u][k] * sWp[k * 32 + c];
                hrow[64 + c] = tanhf(acc);
            } else if (t1 < 112) {
                int j = t1 - 96;
                int jj = j & 7;
                float tt = (float)date[n] / 10000.f;
                float div = expf(-(float)(2 * jj) * (logf(10000.f) / 16.f));
                float a = tt * div;
                hrow[96 + j] = (j < 8) ? sinf(a) : cosf(a);
            }
        }
    }
}

// ---------------- fp16 split conversions ----------------
// which=0 -> src g_h0 (K=112), which=1 -> src g_out1 (K=256). Device-side select.
__global__ void __launch_bounds__(256) k_cvtA(int which, int srcK, int N) {
    const float* src = which ? g_out1 : g_h0;
    int row = blockIdx.x;
    int k = threadIdx.x;
    float v = (row < N && k < srcK) ? src[(size_t)row * srcK + k] : 0.f;
    __half h = __float2half(v);
    __half l = __float2half(v - __half2float(h));
    g_Ah[(size_t)row * 256 + k] = h;
    g_Al[(size_t)row * 256 + k] = l;
}

__global__ void __launch_bounds__(256) k_cvtW(const float* __restrict__ Wl0,
                                              const float* __restrict__ Wr0,
                                              const float* __restrict__ Wl1,
                                              const float* __restrict__ Wr1) {
    int n = blockIdx.x;
    int z = blockIdx.y;
    int l = blockIdx.z;
    int k = threadIdx.x;
    int srcK = (l == 0) ? IN0 : HID;
    const float* W = (l == 0) ? ((z < 5) ? Wl0 : Wr0) : ((z < 5) ? Wl1 : Wr1);
    int zz = z % 5;
    float v = (k < srcK) ? W[((size_t)zz * srcK + k) * HID + n] : 0.f;
    __half h = __float2half(v);
    __half lo = __float2half(v - __half2float(h));
    size_t di = ((size_t)(l * 10 + z) * 256 + n) * 256 + k;
    g_Wth[di] = h;
    g_Wtl[di] = lo;
}

// ---------------- fp16-split GEMM via mma.sync ---------------------------------
// CTA: 128 threads (4 warps), tile 64(M) x 64(N); warp tile 32x32.
// z<5 (xl, feeds values): 3-pass split  D = Ah*Bh + Ah*Bl + Al*Bh  (err ~2^-22)
// z>=5 (xr, feeds scores only): 1-pass  D = Ah*Bh                  (err ~2^-11,
//   -> score error ~1.6e-4 absolute, output impact <~2e-4: within budget)
__global__ void __launch_bounds__(128) k_mma(int Nn, int layer, int K) {
    __shared__ __half sAh[64 * 40];
    __shared__ __half sAl[64 * 40];
    __shared__ __half sBh[64 * 40];
    __shared__ __half sBl[64 * 40];
    int tid = threadIdx.x;
    int lane = tid & 31, wid = tid >> 5;
    int wm = wid & 1, wn = wid >> 1;               // warp tile: (wm*32, wn*32)
    int row0 = blockIdx.x * 64;
    int nb = blockIdx.y * 64;
    int z = blockIdx.z;
    int full = (z < 5);                            // CTA-uniform

    uint32_t uAh = smem_u32(sAh), uAl = smem_u32(sAl);
    uint32_t uBh = smem_u32(sBh), uBl = smem_u32(sBl);

    const uint4* Ah4 = (const uint4*)g_Ah;
    const uint4* Al4 = (const uint4*)g_Al;
    const uint4* Wh4 = (const uint4*)g_Wth;
    const uint4* Wl4 = (const uint4*)g_Wtl;
    size_t wrow0 = (size_t)(layer * 10 + z) * 256 + nb;

    int lr = lane & 7, g = lane >> 3;
    uint32_t offA = (uint32_t)((wm * 32 + (g & 1) * 8 + lr) * 80 + ((g >> 1) * 8) * 2);
    uint32_t offB = (uint32_t)((wn * 32 + (g >> 1) * 8 + lr) * 80 + ((g & 1) * 8) * 2);

    float acc[2][4][4] = {};
    for (int k0 = 0; k0 < K; k0 += 32) {
        #pragma unroll
        for (int it = 0; it < 2; it++) {
            int idx = tid + it * 128;              // 0..255
            int row = idx >> 2, q = idx & 3;
            size_t ga = (size_t)(row0 + row) * 32 + (k0 >> 3) + q;
            size_t gb = (wrow0 + row) * 32 + (k0 >> 3) + q;
            *(uint4*)((char*)sAh + row * 80 + q * 16) = Ah4[ga];
            *(uint4*)((char*)sBh + row * 80 + q * 16) = Wh4[gb];
            if (full) {
                *(uint4*)((char*)sAl + row * 80 + q * 16) = Al4[ga];
                *(uint4*)((char*)sBl + row * 80 + q * 16) = Wl4[gb];
            }
        }
        __syncthreads();
        #pragma unroll
        for (int ks = 0; ks < 32; ks += 16) {
            uint32_t kb = (uint32_t)(ks * 2);
            uint32_t a[2][4], bh[4][2];
            #pragma unroll
            for (int j8 = 0; j8 < 2; j8++)
                LDSM_X4(bh[2 * j8][0], bh[2 * j8][1], bh[2 * j8 + 1][0], bh[2 * j8 + 1][1],
                        uBh + offB + kb + (uint32_t)(j8 * 16 * 80));
            #pragma unroll
            for (int i = 0; i < 2; i++)
                LDSM_X4(a[i][0], a[i][1], a[i][2], a[i][3],
                        uAh + offA + kb + (uint32_t)(i * 16 * 80));
            #pragma unroll
            for (int i = 0; i < 2; i++)
                #pragma unroll
                for (int j = 0; j < 4; j++) { MMA16816(acc[i][j], a[i], bh[j]); }
            if (full) {
                uint32_t bl[4][2];
                #pragma unroll
                for (int j8 = 0; j8 < 2; j8++)
                    LDSM_X4(bl[2 * j8][0], bl[2 * j8][1], bl[2 * j8 + 1][0], bl[2 * j8 + 1][1],
                            uBl + offB + kb + (uint32_t)(j8 * 16 * 80));
                #pragma unroll
                for (int i = 0; i < 2; i++)
                    #pragma unroll
                    for (int j = 0; j < 4; j++) { MMA16816(acc[i][j], a[i], bl[j]); }
                #pragma unroll
                for (int i = 0; i < 2; i++)
                    LDSM_X4(a[i][0], a[i][1], a[i][2], a[i][3],
                            uAl + offA + kb + (uint32_t)(i * 16 * 80));
                #pragma unroll
                for (int i = 0; i < 2; i++)
                    #pragma unroll
                    for (int j = 0; j < 4; j++) { MMA16816(acc[i][j], a[i], bh[j]); }
            }
        }
        __syncthreads();
    }
    float* base = ((z < 5) ? g_xl : g_xr) + (size_t)(z % 5) * Nn * HID;
    #pragma unroll
    for (int i = 0; i < 2; i++) {
        #pragma unroll
        for (int j = 0; j < 4; j++) {
            int m = row0 + wm * 32 + i * 16 + (lane >> 2);
            int nn = nb + wn * 32 + j * 8 + (lane & 3) * 2;
            if (m < Nn)
                *(float2*)&base[(size_t)m * HID + nn] = make_float2(acc[i][j][0], acc[i][j][1]);
            if (m + 8 < Nn)
                *(float2*)&base[(size_t)(m + 8) * HID + nn] = make_float2(acc[i][j][2], acc[i][j][3]);
        }
    }
}

// ---------------- fused GATv2 layer (exact R13 body: measured best) ------------
__global__ void __launch_bounds__(256) k_gat(const float* __restrict__ att,
                                             int N, int E, int layer, int which) {
    const unsigned F = 0xffffffffu;
    int w = (blockIdx.x * blockDim.x + threadIdx.x) >> 5;
    int lane = threadIdx.x & 31;
    if (w >= N) return;
    int d = w;
    float4 A0 = *(const float4*)&g_bsum[layer][lane * 8];
    float4 A1 = *(const float4*)&g_bsum[layer][lane * 8 + 4];
    for (int r = 0; r < R_REL; r++) {
        int beg = g_off[r * N + d], num = g_cnt[r * N + d];
        const float* xlbase = g_xl + (size_t)r * N * HID;
        const float4* xr4 = (const float4*)(g_xr + ((size_t)r * N + d) * HID + lane * 8);
        float4 r0 = xr4[0], r1 = xr4[1];
        const float4* at4 = (const float4*)(att + r * HID + lane * 8);
        float4 a0 = at4[0], a1 = at4[1];
        float t0 = 0.f, t1 = 0.f, t2 = 0.f, t3 = 0.f;
        float t4 = 0.f, t5 = 0.f, t6 = 0.f, t7 = 0.f;
        float denom = 0.f;
        const int* srcs = g_csr + (size_t)r * E + beg;
        for (int base = 0; base < num; base += 32) {
            int my = (base + lane < num) ? srcs[base + lane] : 0;
            int lim = min(32, num - base);
            for (int q = 0; q < lim; q++) {
                int src = __shfl_sync(F, my, q);
                const float4* xl = (const float4*)(xlbase + (size_t)src * HID + lane * 8);
                float4 l0 = xl[0], l1 = xl[1];
                float s = lrelu(l0.x + r0.x) * a0.x + lrelu(l0.y + r0.y) * a0.y
                        + lrelu(l0.z + r0.z) * a0.z + lrelu(l0.w + r0.w) * a0.w
                        + lrelu(l1.x + r1.x) * a1.x + lrelu(l1.y + r1.y) * a1.y
                        + lrelu(l1.z + r1.z) * a1.z + lrelu(l1.w + r1.w) * a1.w;
                s += __shfl_xor_sync(F, s, 4);
                s += __shfl_xor_sync(F, s, 2);
                s += __shfl_xor_sync(F, s, 1);
                float ex = expf(s);
                denom += ex;
                t0 += ex * l0.x; t1 += ex * l0.y; t2 += ex * l0.z; t3 += ex * l0.w;
                t4 += ex * l1.x; t5 += ex * l1.y; t6 += ex * l1.z; t7 += ex * l1.w;
            }
        }
        float inv = 1.f / (denom + 1e-16f);
        A0.x += t0 * inv; A0.y += t1 * inv; A0.z += t2 * inv; A0.w += t3 * inv;
        A1.x += t4 * inv; A1.y += t5 * inv; A1.z += t6 * inv; A1.w += t7 * inv;
    }
    A0.x = fmaxf(A0.x, 0.f); A0.y = fmaxf(A0.y, 0.f);
    A0.z = fmaxf(A0.z, 0.f); A0.w = fmaxf(A0.w, 0.f);
    A1.x = fmaxf(A1.x, 0.f); A1.y = fmaxf(A1.y, 0.f);
    A1.z = fmaxf(A1.z, 0.f); A1.w = fmaxf(A1.w, 0.f);
    float* outbuf = which ? g_out2 : g_out1;
    float* hp = outbuf + (size_t)d * HID + lane * 8;
    *(float4*)hp = A0; *(float4*)(hp + 4) = A1;
}

// output MLP
__global__ void __launch_bounds__(256) k_mlp(const float* __restrict__ W1,
                                             const float* __restrict__ b1,
                                             const float* __restrict__ W2,
                                             const float* __restrict__ b2,
                                             float* __restrict__ out, int N) {
    __shared__ float sh[HID][17];
    __shared__ float so[16][129];
    int t = threadIdx.x;
    int n0 = blockIdx.x * 16;
    for (int i = t; i < 16 * HID; i += 256) {
        int u = i >> 8, c = i & (HID - 1);
        int n = n0 + u;
        sh[c][u] = (n < N) ? g_out2[(size_t)n * HID + c] : 0.f;
    }
    __syncthreads();
    int ct = t & 127, ug = t >> 7;
    float acc[8];
    float bb = b1[ct];
    #pragma unroll
    for (int j = 0; j < 8; j++) acc[j] = bb;
    for (int k = 0; k < HID; k++) {
        float wv = W1[k * 128 + ct];
        #pragma unroll
        for (int j = 0; j < 8; j++) acc[j] += sh[k][ug * 8 + j] * wv;
    }
    #pragma unroll
    for (int j = 0; j < 8; j++) so[ug * 8 + j][ct] = fmaxf(acc[j], 0.f);
    __syncthreads();
    if (t < 48) {
        int u = t / 3, j = t - u * 3;
        int n = n0 + u;
        if (n < N) {
            float a = b2[j];
            #pragma unroll 4
            for (int k = 0; k < 128; k++) a += so[u][k] * W2[k * 3 + j];
            out[(size_t)n * 3 + j] = a;
        }
    }
}

// ---------------- launch ----------------
extern "C" void kernel_launch(void* const* d_in, const int* in_sizes, int n_in,
                              void* d_out, int out_size) {
    const float* x     = (const float*)d_in[0];
    const int*   date  = (const int*)d_in[1];
    const int*   ei    = (const int*)d_in[2];
    const float* pW    = (const float*)d_in[3];
    const float* pb    = (const float*)d_in[4];
    const float* Wl0   = (const float*)d_in[5];
    const float* Wr0   = (const float*)d_in[6];
    const float* att0  = (const float*)d_in[7];
    const float* b0    = (const float*)d_in[8];
    const float* Wl1   = (const float*)d_in[9];
    const float* Wr1   = (const float*)d_in[10];
    const float* att1  = (const float*)d_in[11];
    const float* b1    = (const float*)d_in[12];
    const float* oW1   = (const float*)d_in[16];
    const float* ob1   = (const float*)d_in[17];
    const float* oW2   = (const float*)d_in[18];
    const float* ob2   = (const float*)d_in[19];
    float* out = (float*)d_out;

    int N = in_sizes[0] / IN_DIM;
    int E = in_sizes[2] / (R_REL * 2);

    // ---- CSR build ----
    k_hist<<<(R_REL * E + 255) / 256, 256>>>(ei, N, E);
    k_scan<<<R_REL, 1024>>>(N);
    k_scatter<<<(R_REL * E + 255) / 256, 256>>>(ei, N, E);

    // ---- PE + h0 ----
    k_pearl<<<(N * 32 + 255) / 256, 256>>>(x, N, E);           // profiled slot
    k_bsum<<<1, HID>>>(b0, b1);
    k_build_h0<<<(N + 7) / 8, 256>>>(x, date, pW, pb, N);

    // ---- weight conversion ----
    dim3 wgrid(256, 10, 2);
    k_cvtW<<<wgrid, 256>>>(Wl0, Wr0, Wl1, Wr1);

    int mtiles = (N + 63) / 64;
    dim3 mma_grid(mtiles, 4, 10);
    int gat_grid = (N * 32 + 255) / 256;

    // ---- GNN layer 0 (K padded 112 -> 128) ----
    k_cvtA<<<NPAD, 256>>>(0, IN0, N);
    k_mma<<<mma_grid, 128>>>(N, 0, 128);
    k_gat<<<gat_grid, 256>>>(att0, N, E, 0, 0);

    // ---- GNN layer 1 (K = 256) ----
    k_cvtA<<<NPAD, 256>>>(1, HID, N);
    k_mma<<<mma_grid, 128>>>(N, 1, 256);
    k_gat<<<gat_grid, 256>>>(att1, N, E, 1, 1);

    // ---- output MLP ----
    k_mlp<<<(N + 15) / 16, 256>>>(oW1, ob1, oW2, ob2, out, N);

    // ---- tail: restore g_cnt ----
    k_zero_cnt<<<(R_REL * N + 255) / 256, 256>>>(N);
}